// round 7
// baseline (speedup 1.0000x reference)
#include <cuda_runtime.h>
#include <cuda_bf16.h>
#include <cstdint>

#define B_ 4
#define N_ 1024
#define D_ 768
#define H_ 12
#define ND3_ 2304
typedef unsigned long long u64t;

__device__ float g_q[B_ * H_ * N_ * 64];
__device__ float g_k[B_ * H_ * N_ * 64];
__device__ float g_v[B_ * H_ * N_ * 64];
__device__ unsigned short g_bidx[(size_t)B_ * N_ * N_];
__device__ __nv_bfloat16 g_a2[4096 * 1536];  // [m][hi(768)|lo(768)]
__device__ __nv_bfloat16 g_b2[2304 * 1536];  // [n][hi|lo]  (W transposed)

__device__ __forceinline__ void ffma2(u64t& d, u64t a, u64t b) {
    asm("fma.rn.f32x2 %0, %1, %2, %0;" : "+l"(d) : "l"(a), "l"(b));
}
__device__ __forceinline__ u64t dup2(float x) {
    u64t r;
    asm("mov.b64 %0, {%1, %1};" : "=l"(r) : "f"(x));
    return r;
}
__device__ __forceinline__ uint32_t smem_u32(const void* p) {
    uint32_t a;
    asm("{ .reg .u64 t; cvta.to.shared.u64 t, %1; cvt.u32.u64 %0, t; }"
        : "=r"(a) : "l"(p));
    return a;
}
__device__ __forceinline__ void mma16816(float* c, const uint32_t* a,
                                         const uint32_t* b) {
    asm volatile(
        "mma.sync.aligned.m16n8k16.row.col.f32.bf16.bf16.f32 "
        "{%0,%1,%2,%3}, {%4,%5,%6,%7}, {%8,%9}, {%0,%1,%2,%3};"
        : "+f"(c[0]), "+f"(c[1]), "+f"(c[2]), "+f"(c[3])
        : "r"(a[0]), "r"(a[1]), "r"(a[2]), "r"(a[3]), "r"(b[0]), "r"(b[1]));
}
__device__ __forceinline__ void ldsm4(uint32_t* r, uint32_t addr) {
    asm volatile("ldmatrix.sync.aligned.m8n8.x4.shared.b16 {%0,%1,%2,%3}, [%4];"
                 : "=r"(r[0]), "=r"(r[1]), "=r"(r[2]), "=r"(r[3]) : "r"(addr));
}
__device__ __forceinline__ void cp16(uint32_t dst, const void* src) {
    asm volatile("cp.async.cg.shared.global [%0], [%1], 16;" :: "r"(dst), "l"(src));
}

// ------------- mma.sync bf16-split GEMM: 128x128 tile, KC=32, 3-stage -------
#define GSTAGE_BYTES 20480
#define GEMM_SMEM (3 * GSTAGE_BYTES)

template <bool IS_QKV>
__global__ __launch_bounds__(256) void mma_gemm(const float* __restrict__ bias,
                                                float* __restrict__ out) {
    extern __shared__ char smem[];
    const int tid = threadIdx.x, wid = tid >> 5, lid = tid & 31;
    const int m0 = blockIdx.y * 128, n0 = blockIdx.x * 128;
    const int mw = wid >> 2, nw = wid & 3;
    const uint32_t sbase = smem_u32(smem);

    const __nv_bfloat16* a2 = g_a2 + (size_t)m0 * 1536;
    const __nv_bfloat16* b2 = g_b2 + (size_t)n0 * 1536;

    const int lr0 = tid >> 2, ls0 = tid & 3;
    const int lr1 = (tid + 256) >> 2, ls1 = (tid + 256) & 3;

    float acc[4][4][4];
#pragma unroll
    for (int i = 0; i < 4; i++)
#pragma unroll
        for (int j = 0; j < 4; j++)
#pragma unroll
            for (int k = 0; k < 4; k++) acc[i][j][k] = 0.0f;

    auto load_chunk = [&](int c, int s) {
        int p = c / 24, cc = c % 24;
        int aoff = (p == 2 ? 768 : 0) + cc * 32;
        int boff = (p == 1 ? 768 : 0) + cc * 32;
        uint32_t da = sbase + s * GSTAGE_BYTES;
        uint32_t db = da + 10240;
        cp16(da + lr0 * 80 + ls0 * 16, a2 + (size_t)lr0 * 1536 + aoff + ls0 * 8);
        cp16(da + lr1 * 80 + ls1 * 16, a2 + (size_t)lr1 * 1536 + aoff + ls1 * 8);
        cp16(db + lr0 * 80 + ls0 * 16, b2 + (size_t)lr0 * 1536 + boff + ls0 * 8);
        cp16(db + lr1 * 80 + ls1 * 16, b2 + (size_t)lr1 * 1536 + boff + ls1 * 8);
        asm volatile("cp.async.commit_group;" ::: "memory");
    };

    load_chunk(0, 0);
    load_chunk(1, 1);

    const int q = lid >> 3, r = lid & 7;
    const int aRow = mw * 64 + (q & 1) * 8 + r;
    const int aCol = (q >> 1) * 16;
    const int bRowE = nw * 32 + (q >> 1) * 8 + r;
    const int bCol = (q & 1) * 16;

    int s = 0, sn = 2;
    for (int c = 0; c < 72; c++) {
        asm volatile("cp.async.wait_group 1;" ::: "memory");
        __syncthreads();
        if (c + 2 < 72) {
            load_chunk(c + 2, sn);
            if (++sn == 3) sn = 0;
        }
        uint32_t sAb = sbase + s * GSTAGE_BYTES;
        uint32_t sBb = sAb + 10240;
#pragma unroll
        for (int ks = 0; ks < 2; ks++) {
            int koff = ks * 32;
            uint32_t bfr[4][2];
#pragma unroll
            for (int p = 0; p < 2; p++) {
                uint32_t t[4];
                ldsm4(t, sBb + (bRowE + p * 16) * 80 + koff + bCol);
                bfr[p * 2 + 0][0] = t[0];
                bfr[p * 2 + 0][1] = t[1];
                bfr[p * 2 + 1][0] = t[2];
                bfr[p * 2 + 1][1] = t[3];
            }
#pragma unroll
            for (int mt = 0; mt < 4; mt++) {
                uint32_t afr[4];
                ldsm4(afr, sAb + (aRow + mt * 16) * 80 + koff + aCol);
#pragma unroll
                for (int nt = 0; nt < 4; nt++) mma16816(acc[mt][nt], afr, bfr[nt]);
            }
        }
        if (++s == 3) s = 0;
    }

#pragma unroll
    for (int mt = 0; mt < 4; mt++) {
#pragma unroll
        for (int half = 0; half < 2; half++) {
            int m = m0 + mw * 64 + mt * 16 + (lid >> 2) + half * 8;
            int mb = m >> 10, mr = m & 1023;
#pragma unroll
            for (int nt = 0; nt < 4; nt++) {
                int ng = n0 + nw * 32 + nt * 8 + 2 * (lid & 3);
                float2 v =
                    make_float2(acc[mt][nt][half * 2], acc[mt][nt][half * 2 + 1]);
                if (IS_QKV) {
                    int which = ng / D_, nm = ng % D_, hh = nm >> 6, c0 = nm & 63;
                    float* dst = (which == 0) ? g_q : (which == 1) ? g_k : g_v;
                    *(float2*)&dst[(((size_t)(mb * H_ + hh) * N_ + mr) << 6) + c0] = v;
                } else {
                    v.x += bias[ng];
                    v.y += bias[ng + 1];
                    *(float2*)&out[(size_t)m * D_ + ng] = v;
                }
            }
        }
    }
}

// ---------------- bf16 hi/lo split preps ----------------
__global__ __launch_bounds__(256) void split_a(const float* __restrict__ X) {
    int idx = blockIdx.x * 256 + threadIdx.x;
    float4 v = ((const float4*)X)[idx];
    int m = idx / 192, kq = (idx % 192) * 4;
    __nv_bfloat16 h0 = __float2bfloat16(v.x), h1 = __float2bfloat16(v.y);
    __nv_bfloat16 h2 = __float2bfloat16(v.z), h3 = __float2bfloat16(v.w);
    __nv_bfloat16 l0 = __float2bfloat16(v.x - __bfloat162float(h0));
    __nv_bfloat16 l1 = __float2bfloat16(v.y - __bfloat162float(h1));
    __nv_bfloat16 l2 = __float2bfloat16(v.z - __bfloat162float(h2));
    __nv_bfloat16 l3 = __float2bfloat16(v.w - __bfloat162float(h3));
    __nv_bfloat16* rr = g_a2 + (size_t)m * 1536 + kq;
    rr[0] = h0; rr[1] = h1; rr[2] = h2; rr[3] = h3;
    rr[768] = l0; rr[769] = l1; rr[770] = l2; rr[771] = l3;
}

__global__ void split_wt(const float* __restrict__ W, int ncols) {
    __shared__ float t[32][33];
    int k0 = blockIdx.y * 32, n0 = blockIdx.x * 32;
    int tx = threadIdx.x, ty = threadIdx.y;  // (32,8)
#pragma unroll
    for (int i = 0; i < 4; i++)
        t[ty * 4 + i][tx] = W[(size_t)(k0 + ty * 4 + i) * ncols + n0 + tx];
    __syncthreads();
#pragma unroll
    for (int i = 0; i < 4; i++) {
        int n = n0 + ty * 4 + i;
        float x = t[tx][ty * 4 + i];
        __nv_bfloat16 h = __float2bfloat16(x);
        __nv_bfloat16 l = __float2bfloat16(x - __bfloat162float(h));
        g_b2[(size_t)n * 1536 + k0 + tx] = h;
        g_b2[(size_t)n * 1536 + 768 + k0 + tx] = l;
    }
}

// ---------------- bucket-index precompute ----------------
__device__ __forceinline__ int bucket_fn(int d) {
    int ret = (d > 0) ? 16 : 0;
    int n = (d < 0) ? -d : d;
    int v;
    if (n < 8) v = n;
    else { v = 33 - __clz(n * n); v = (v > 15) ? 15 : v; }
    return ret + v;
}

__global__ __launch_bounds__(256) void bidx_kernel(const float* __restrict__ coords) {
    __shared__ short cjx[1024], cjy[1024];
    const int b = blockIdx.y, i0 = blockIdx.x * 16, tid = threadIdx.x;
    for (int t = tid; t < 1024; t += 256) {
        float2 c = *(const float2*)(coords + ((size_t)b * 1024 + t) * 2);
        cjx[t] = (short)(int)(c.x * 128.0f);
        cjy[t] = (short)(int)(c.y * 128.0f);
    }
    __syncthreads();
    unsigned short* outb = g_bidx + (size_t)b * N_ * N_ + (size_t)i0 * N_;
#pragma unroll
    for (int qq = 0; qq < 16; ++qq) {
        int item = tid + qq * 256;
        int i = item >> 8, j = (item & 255) * 4;
        int cx = cjx[i0 + i], cy = cjy[i0 + i];
        ushort4 r;
        r.x = (unsigned short)((bucket_fn(cx - cjx[j]) << 5) | bucket_fn(cy - cjy[j]));
        r.y = (unsigned short)((bucket_fn(cx - cjx[j + 1]) << 5) | bucket_fn(cy - cjy[j + 1]));
        r.z = (unsigned short)((bucket_fn(cx - cjx[j + 2]) << 5) | bucket_fn(cy - cjy[j + 2]));
        r.w = (unsigned short)((bucket_fn(cx - cjx[j + 3]) << 5) | bucket_fn(cy - cjy[j + 3]));
        *(ushort4*)(outb + (size_t)i * N_ + j) = r;
    }
}

// ---------------- attention: fixed-max softmax, float4 PV ----------------
#define AT_QT 0
#define AT_KT 8192
#define AT_VS 12544
#define AT_PS 16896
#define AT_TBL 25600
#define AT_EJS 26624
#define ATTN_SMEM_BYTES (26688 * 4)

__global__ __launch_bounds__(256, 2) void attn2_kernel(
    const float* __restrict__ elev, const float* __restrict__ bias_table,
    const float* __restrict__ alphap) {
    extern __shared__ float smf[];
    float(*qt)[128] = (float(*)[128])(smf + AT_QT);
    float(*kt)[68] = (float(*)[68])(smf + AT_KT);
    float(*vs)[68] = (float(*)[68])(smf + AT_VS);
    float(*ps)[68] = (float(*)[68])(smf + AT_PS);
    float* tbl = smf + AT_TBL;
    float* ejs = smf + AT_EJS;

    const int i0 = blockIdx.x * 128, h = blockIdx.y, b = blockIdx.z;
    const int tid = threadIdx.x;
    const int tx = tid & 15, ty = tid >> 4;

    for (int t = tid; t < 1024; t += 256) tbl[t] = bias_table[t * H_ + h];

    const float* qb = g_q + (((size_t)(b * H_ + h) * N_ + i0) << 6);
#pragma unroll
    for (int p = 0; p < 8; ++p) {
        int idx = tid + p * 256;
        int i = idx & 127, dq = idx >> 7;
        float4 f = *(const float4*)(qb + i * 64 + dq * 4);
        qt[dq * 4 + 0][i] = f.x; qt[dq * 4 + 1][i] = f.y;
        qt[dq * 4 + 2][i] = f.z; qt[dq * 4 + 3][i] = f.w;
    }

    float eir[8];
#pragma unroll
    for (int i = 0; i < 8; ++i)
        eir[i] = elev[b * N_ + i0 + ty * 8 + i] * (1.0f / 1000.0f);
    const float alpha = *alphap;

    u64t oacc[8][2];
    float lrow[8];
#pragma unroll
    for (int i = 0; i < 8; ++i) {
        oacc[i][0] = 0ULL; oacc[i][1] = 0ULL;
        lrow[i] = 0.0f;
    }

    const float* kb0 = g_k + (((size_t)(b * H_ + h) * N_) << 6);
    const float* vb0 = g_v + (((size_t)(b * H_ + h) * N_) << 6);
    const unsigned short* bidxb = g_bidx + (size_t)b * N_ * N_ + (size_t)i0 * N_;

    for (int jt = 0; jt < 16; ++jt) {
        const int j0 = jt * 64;
        __syncthreads();
        const float* kb = kb0 + ((size_t)j0 << 6);
        const float* vb = vb0 + ((size_t)j0 << 6);
#pragma unroll
        for (int p = 0; p < 4; ++p) {
            int idx = tid + p * 256;
            int j = idx & 63, dq = idx >> 6;
            float4 f = *(const float4*)(kb + j * 64 + dq * 4);
            kt[dq * 4 + 0][j] = f.x; kt[dq * 4 + 1][j] = f.y;
            kt[dq * 4 + 2][j] = f.z; kt[dq * 4 + 3][j] = f.w;
            int dv = idx & 15, jv = idx >> 4;
            *(float4*)&vs[jv][dv * 4] = *(const float4*)(vb + jv * 64 + dv * 4);
        }
        if (tid < 64) ejs[tid] = elev[b * N_ + j0 + tid] * (1.0f / 1000.0f);
        __syncthreads();

        // S = Q K^T (row-pairs packed)
        u64t s2[4][4];
#pragma unroll
        for (int i = 0; i < 4; i++)
#pragma unroll
            for (int j = 0; j < 4; j++) s2[i][j] = 0ULL;
#pragma unroll 8
        for (int d = 0; d < 64; ++d) {
            ulonglong2 qa0 = *(const ulonglong2*)&qt[d][ty * 8];
            ulonglong2 qa1 = *(const ulonglong2*)&qt[d][ty * 8 + 4];
            float4 kf = *(const float4*)&kt[d][tx * 4];
            u64t ap[4] = {qa0.x, qa0.y, qa1.x, qa1.y};
            u64t bbv[4] = {dup2(kf.x), dup2(kf.y), dup2(kf.z), dup2(kf.w)};
#pragma unroll
            for (int rp = 0; rp < 4; ++rp)
#pragma unroll
                for (int c = 0; c < 4; ++c) ffma2(s2[rp][c], ap[rp], bbv[c]);
        }

        // biases + exp (scores bounded: no running max needed)
        float ej[4] = {ejs[tx * 4 + 0], ejs[tx * 4 + 1], ejs[tx * 4 + 2],
                       ejs[tx * 4 + 3]};
#pragma unroll
        for (int i = 0; i < 8; ++i) {
            int rp = i >> 1, hi = i & 1;
            float sv[4];
#pragma unroll
            for (int c = 0; c < 4; ++c) {
                float2 v = *(float2*)&s2[rp][c];
                sv[c] = hi ? v.y : v.x;
            }
            uint2 bx = *(const uint2*)(bidxb + (size_t)(ty * 8 + i) * N_ + j0 + tx * 4);
            int bi[4] = {(int)(bx.x & 0xffff), (int)(bx.x >> 16),
                         (int)(bx.y & 0xffff), (int)(bx.y >> 16)};
            float e_i = eir[i];
            float p[4];
#pragma unroll
            for (int c = 0; c < 4; ++c) {
                float eb = fminf(fmaxf(-alpha * fmaxf(ej[c] - e_i, 0.f), -10.f), 0.f);
                p[c] = __expf(sv[c] * 0.125f + tbl[bi[c]] + eb);
            }
            lrow[i] += (p[0] + p[1]) + (p[2] + p[3]);
            *(float4*)&ps[ty * 8 + i][tx * 4] = make_float4(p[0], p[1], p[2], p[3]);
        }
        __syncthreads();

        // O += P V  (float4 ps loads, 4-wide j blocks)
#pragma unroll 4
        for (int jb = 0; jb < 16; ++jb) {
            float4 pr[8];
#pragma unroll
            for (int i = 0; i < 8; ++i)
                pr[i] = *(const float4*)&ps[ty * 8 + i][jb * 4];
#pragma unroll
            for (int c = 0; c < 4; ++c) {
                ulonglong2 v2 = *(const ulonglong2*)&vs[jb * 4 + c][tx * 4];
#pragma unroll
                for (int i = 0; i < 8; ++i) {
                    float pv = (c == 0) ? pr[i].x : (c == 1) ? pr[i].y
                               : (c == 2) ? pr[i].z : pr[i].w;
                    u64t pp = dup2(pv);
                    ffma2(oacc[i][0], pp, v2.x);
                    ffma2(oacc[i][1], pp, v2.y);
                }
            }
        }
    }

#pragma unroll
    for (int i = 0; i < 8; ++i) {
        float l = lrow[i];
        l += __shfl_xor_sync(0xffffffff, l, 1);
        l += __shfl_xor_sync(0xffffffff, l, 2);
        l += __shfl_xor_sync(0xffffffff, l, 4);
        l += __shfl_xor_sync(0xffffffff, l, 8);
        float inv = 1.0f / l;
        float2 o0 = *(float2*)&oacc[i][0];
        float2 o1 = *(float2*)&oacc[i][1];
        int row = i0 + ty * 8 + i;
        float ov[4] = {o0.x * inv, o0.y * inv, o1.x * inv, o1.y * inv};
        __nv_bfloat16* rr = g_a2 + (size_t)(b * N_ + row) * 1536 + h * 64 + tx * 4;
        __nv_bfloat16 hbuf[4], lbuf[4];
#pragma unroll
        for (int c = 0; c < 4; ++c) {
            hbuf[c] = __float2bfloat16(ov[c]);
            lbuf[c] = __float2bfloat16(ov[c] - __bfloat162float(hbuf[c]));
        }
        *(uint2*)rr = *(uint2*)hbuf;
        *(uint2*)(rr + 768) = *(uint2*)lbuf;
    }
}

extern "C" void kernel_launch(void* const* d_in, const int* in_sizes, int n_in,
                              void* d_out, int out_size) {
    const float* x = (const float*)d_in[0];
    const float* coords = (const float*)d_in[1];
    const float* elev = (const float*)d_in[2];
    const float* W_qkv = (const float*)d_in[3];
    const float* W_proj = (const float*)d_in[4];
    const float* b_proj = (const float*)d_in[5];
    const float* bias_table = (const float*)d_in[6];
    const float* alpha = (const float*)d_in[7];
    float* out = (float*)d_out;

    cudaFuncSetAttribute(attn2_kernel, cudaFuncAttributeMaxDynamicSharedMemorySize,
                         ATTN_SMEM_BYTES);
    cudaFuncSetAttribute(mma_gemm<true>, cudaFuncAttributeMaxDynamicSharedMemorySize,
                         GEMM_SMEM);
    cudaFuncSetAttribute(mma_gemm<false>, cudaFuncAttributeMaxDynamicSharedMemorySize,
                         GEMM_SMEM);

    // order chosen so the ncu capture (launch index 3) hits mma_gemm<true>
    split_a<<<3072, 256>>>(x);
    split_wt<<<dim3(ND3_ / 32, 24), dim3(32, 8)>>>(W_qkv, ND3_);
    bidx_kernel<<<dim3(64, B_), 256>>>(coords);
    mma_gemm<true><<<dim3(ND3_ / 128, 32), 256, GEMM_SMEM>>>(nullptr, nullptr);
    attn2_kernel<<<dim3(N_ / 128, H_, B_), 256, ATTN_SMEM_BYTES>>>(elev, bias_table, alpha);
    split_wt<<<dim3(D_ / 32, 24), dim3(32, 8)>>>(W_proj, D_);
    mma_gemm<false><<<dim3(D_ / 128, 32), 256, GEMM_SMEM>>>(b_proj, out);
}

// round 8
// speedup vs baseline: 1.0584x; 1.0584x over previous
#include <cuda_runtime.h>
#include <cuda_bf16.h>
#include <cstdint>

#define B_ 4
#define N_ 1024
#define D_ 768
#define H_ 12
#define ND3_ 2304
typedef unsigned long long u64t;

__device__ float g_q[B_ * H_ * N_ * 64];
__device__ float g_k[B_ * H_ * N_ * 64];
__device__ float g_v[B_ * H_ * N_ * 64];
__device__ unsigned short g_bidx[(size_t)B_ * N_ * N_];
__device__ __nv_bfloat16 g_a2[4096 * 1536];  // [m][hi(768)|lo(768)]
__device__ __nv_bfloat16 g_b2[2304 * 1536];  // [n][hi|lo]  (W transposed)

__device__ __forceinline__ void ffma2(u64t& d, u64t a, u64t b) {
    asm("fma.rn.f32x2 %0, %1, %2, %0;" : "+l"(d) : "l"(a), "l"(b));
}
__device__ __forceinline__ u64t dup2(float x) {
    u64t r;
    asm("mov.b64 %0, {%1, %1};" : "=l"(r) : "f"(x));
    return r;
}
__device__ __forceinline__ uint32_t smem_u32(const void* p) {
    uint32_t a;
    asm("{ .reg .u64 t; cvta.to.shared.u64 t, %1; cvt.u32.u64 %0, t; }"
        : "=r"(a) : "l"(p));
    return a;
}
__device__ __forceinline__ void mma16816(float* c, const uint32_t* a,
                                         const uint32_t* b) {
    asm volatile(
        "mma.sync.aligned.m16n8k16.row.col.f32.bf16.bf16.f32 "
        "{%0,%1,%2,%3}, {%4,%5,%6,%7}, {%8,%9}, {%0,%1,%2,%3};"
        : "+f"(c[0]), "+f"(c[1]), "+f"(c[2]), "+f"(c[3])
        : "r"(a[0]), "r"(a[1]), "r"(a[2]), "r"(a[3]), "r"(b[0]), "r"(b[1]));
}
__device__ __forceinline__ void ldsm4(uint32_t* r, uint32_t addr) {
    asm volatile("ldmatrix.sync.aligned.m8n8.x4.shared.b16 {%0,%1,%2,%3}, [%4];"
                 : "=r"(r[0]), "=r"(r[1]), "=r"(r[2]), "=r"(r[3]) : "r"(addr));
}
__device__ __forceinline__ void cp16(uint32_t dst, const void* src) {
    asm volatile("cp.async.cg.shared.global [%0], [%1], 16;" :: "r"(dst), "l"(src));
}

// --------- mma.sync bf16-split GEMM: 128x128 tile, KC=64, 3-stage ----------
// Kext = 3*768: pass0 Ah*Bh, pass1 Ah*Bl, pass2 Al*Bh. 144B padded rows.
#define GTILE_BYTES 18432           // 128 rows * 144B
#define GSTAGE_BYTES (2 * GTILE_BYTES)
#define GEMM_SMEM (3 * GSTAGE_BYTES)  // 110592

template <bool IS_QKV>
__global__ __launch_bounds__(256) void mma_gemm(const float* __restrict__ bias,
                                                float* __restrict__ out) {
    extern __shared__ char smem[];
    const int tid = threadIdx.x, wid = tid >> 5, lid = tid & 31;
    const int m0 = blockIdx.y * 128, n0 = blockIdx.x * 128;
    const int mw = wid >> 2, nw = wid & 3;
    const uint32_t sbase = smem_u32(smem);

    const __nv_bfloat16* a2 = g_a2 + (size_t)m0 * 1536;
    const __nv_bfloat16* b2 = g_b2 + (size_t)n0 * 1536;

    float acc[4][4][4];
#pragma unroll
    for (int i = 0; i < 4; i++)
#pragma unroll
        for (int j = 0; j < 4; j++)
#pragma unroll
            for (int k = 0; k < 4; k++) acc[i][j][k] = 0.0f;

    auto load_chunk = [&](int c, int s) {
        int p = c / 12, cc = c % 12;
        int aoff = (p == 2 ? 768 : 0) + cc * 64;
        int boff = (p == 1 ? 768 : 0) + cc * 64;
        uint32_t da = sbase + s * GSTAGE_BYTES;
        uint32_t db = da + GTILE_BYTES;
#pragma unroll
        for (int i = 0; i < 4; i++) {
            int id = tid + i * 256;
            int row = id >> 3, seg = id & 7;
            cp16(da + row * 144 + seg * 16, a2 + (size_t)row * 1536 + aoff + seg * 8);
            cp16(db + row * 144 + seg * 16, b2 + (size_t)row * 1536 + boff + seg * 8);
        }
        asm volatile("cp.async.commit_group;" ::: "memory");
    };

    load_chunk(0, 0);
    load_chunk(1, 1);

    const int q = lid >> 3, r = lid & 7;
    const int aRow = mw * 64 + (q & 1) * 8 + r;    // + mt*16
    const int aCol = (q >> 1) * 16;                // + ks*32
    const int bRowE = nw * 32 + (q >> 1) * 8 + r;  // + p*16
    const int bCol = (q & 1) * 16;                 // + ks*32

    for (int c = 0; c < 36; c++) {
        int s = c % 3;
        asm volatile("cp.async.wait_group 1;" ::: "memory");
        __syncthreads();
        if (c + 2 < 36) load_chunk(c + 2, (c + 2) % 3);
        uint32_t sAb = sbase + s * GSTAGE_BYTES;
        uint32_t sBb = sAb + GTILE_BYTES;
#pragma unroll
        for (int ks = 0; ks < 4; ks++) {
            int koff = ks * 32;
            uint32_t bfr[4][2];
#pragma unroll
            for (int p = 0; p < 2; p++) {
                uint32_t t[4];
                ldsm4(t, sBb + (bRowE + p * 16) * 144 + koff + bCol);
                bfr[p * 2 + 0][0] = t[0];
                bfr[p * 2 + 0][1] = t[1];
                bfr[p * 2 + 1][0] = t[2];
                bfr[p * 2 + 1][1] = t[3];
            }
#pragma unroll
            for (int mt = 0; mt < 4; mt++) {
                uint32_t afr[4];
                ldsm4(afr, sAb + (aRow + mt * 16) * 144 + koff + aCol);
#pragma unroll
                for (int nt = 0; nt < 4; nt++) mma16816(acc[mt][nt], afr, bfr[nt]);
            }
        }
    }

#pragma unroll
    for (int mt = 0; mt < 4; mt++) {
#pragma unroll
        for (int half = 0; half < 2; half++) {
            int m = m0 + mw * 64 + mt * 16 + (lid >> 2) + half * 8;
            int mb = m >> 10, mr = m & 1023;
#pragma unroll
            for (int nt = 0; nt < 4; nt++) {
                int ng = n0 + nw * 32 + nt * 8 + 2 * (lid & 3);
                float2 v =
                    make_float2(acc[mt][nt][half * 2], acc[mt][nt][half * 2 + 1]);
                if (IS_QKV) {
                    int which = ng / D_, nm = ng % D_, hh = nm >> 6, c0 = nm & 63;
                    float* dst = (which == 0) ? g_q : (which == 1) ? g_k : g_v;
                    *(float2*)&dst[(((size_t)(mb * H_ + hh) * N_ + mr) << 6) + c0] = v;
                } else {
                    v.x += bias[ng];
                    v.y += bias[ng + 1];
                    *(float2*)&out[(size_t)m * D_ + ng] = v;
                }
            }
        }
    }
}

// ------------- merged prep: split_a (blocks 0..3071) + bidx (3072..3327) ----
__device__ __forceinline__ int bucket_fn(int d) {
    int ret = (d > 0) ? 16 : 0;
    int n = (d < 0) ? -d : d;
    int v;
    if (n < 8) v = n;
    else { v = 33 - __clz(n * n); v = (v > 15) ? 15 : v; }
    return ret + v;
}

__global__ __launch_bounds__(256) void prep_kernel(const float* __restrict__ X,
                                                   const float* __restrict__ coords) {
    __shared__ short cjx[1024], cjy[1024];
    const int tid = threadIdx.x;
    if (blockIdx.x < 3072) {
        int idx = blockIdx.x * 256 + tid;
        float4 v = ((const float4*)X)[idx];
        int m = idx / 192, kq = (idx % 192) * 4;
        __nv_bfloat16 h0 = __float2bfloat16(v.x), h1 = __float2bfloat16(v.y);
        __nv_bfloat16 h2 = __float2bfloat16(v.z), h3 = __float2bfloat16(v.w);
        __nv_bfloat16 l0 = __float2bfloat16(v.x - __bfloat162float(h0));
        __nv_bfloat16 l1 = __float2bfloat16(v.y - __bfloat162float(h1));
        __nv_bfloat16 l2 = __float2bfloat16(v.z - __bfloat162float(h2));
        __nv_bfloat16 l3 = __float2bfloat16(v.w - __bfloat162float(h3));
        __nv_bfloat16* rr = g_a2 + (size_t)m * 1536 + kq;
        rr[0] = h0; rr[1] = h1; rr[2] = h2; rr[3] = h3;
        rr[768] = l0; rr[769] = l1; rr[770] = l2; rr[771] = l3;
        return;
    }
    const int bid = blockIdx.x - 3072;
    const int b = bid >> 6, i0 = (bid & 63) * 16;
    for (int t = tid; t < 1024; t += 256) {
        float2 c = *(const float2*)(coords + ((size_t)b * 1024 + t) * 2);
        cjx[t] = (short)(int)(c.x * 128.0f);
        cjy[t] = (short)(int)(c.y * 128.0f);
    }
    __syncthreads();
    unsigned short* outb = g_bidx + (size_t)b * N_ * N_ + (size_t)i0 * N_;
#pragma unroll
    for (int qq = 0; qq < 16; ++qq) {
        int item = tid + qq * 256;
        int i = item >> 8, j = (item & 255) * 4;
        int cx = cjx[i0 + i], cy = cjy[i0 + i];
        ushort4 r;
        r.x = (unsigned short)((bucket_fn(cx - cjx[j]) << 5) | bucket_fn(cy - cjy[j]));
        r.y = (unsigned short)((bucket_fn(cx - cjx[j + 1]) << 5) | bucket_fn(cy - cjy[j + 1]));
        r.z = (unsigned short)((bucket_fn(cx - cjx[j + 2]) << 5) | bucket_fn(cy - cjy[j + 2]));
        r.w = (unsigned short)((bucket_fn(cx - cjx[j + 3]) << 5) | bucket_fn(cy - cjy[j + 3]));
        *(ushort4*)(outb + (size_t)i * N_ + j) = r;
    }
}

__global__ void split_wt(const float* __restrict__ W, int ncols) {
    __shared__ float t[32][33];
    int k0 = blockIdx.y * 32, n0 = blockIdx.x * 32;
    int tx = threadIdx.x, ty = threadIdx.y;  // (32,8)
#pragma unroll
    for (int i = 0; i < 4; i++)
        t[ty * 4 + i][tx] = W[(size_t)(k0 + ty * 4 + i) * ncols + n0 + tx];
    __syncthreads();
#pragma unroll
    for (int i = 0; i < 4; i++) {
        int n = n0 + ty * 4 + i;
        float x = t[tx][ty * 4 + i];
        __nv_bfloat16 h = __float2bfloat16(x);
        __nv_bfloat16 l = __float2bfloat16(x - __bfloat162float(h));
        g_b2[(size_t)n * 1536 + k0 + tx] = h;
        g_b2[(size_t)n * 1536 + 768 + k0 + tx] = l;
    }
}

// ---------------- attention: fixed-max softmax, float4 PV ----------------
#define AT_QT 0
#define AT_KT 8192
#define AT_VS 12544
#define AT_PS 16896
#define AT_TBL 25600
#define AT_EJS 26624
#define ATTN_SMEM_BYTES (26688 * 4)

__global__ __launch_bounds__(256, 2) void attn2_kernel(
    const float* __restrict__ elev, const float* __restrict__ bias_table,
    const float* __restrict__ alphap) {
    extern __shared__ float smf[];
    float(*qt)[128] = (float(*)[128])(smf + AT_QT);
    float(*kt)[68] = (float(*)[68])(smf + AT_KT);
    float(*vs)[68] = (float(*)[68])(smf + AT_VS);
    float(*ps)[68] = (float(*)[68])(smf + AT_PS);
    float* tbl = smf + AT_TBL;
    float* ejs = smf + AT_EJS;

    const int i0 = blockIdx.x * 128, h = blockIdx.y, b = blockIdx.z;
    const int tid = threadIdx.x;
    const int tx = tid & 15, ty = tid >> 4;

    for (int t = tid; t < 1024; t += 256) tbl[t] = bias_table[t * H_ + h];

    const float* qb = g_q + (((size_t)(b * H_ + h) * N_ + i0) << 6);
#pragma unroll
    for (int p = 0; p < 8; ++p) {
        int idx = tid + p * 256;
        int i = idx & 127, dq = idx >> 7;
        float4 f = *(const float4*)(qb + i * 64 + dq * 4);
        qt[dq * 4 + 0][i] = f.x; qt[dq * 4 + 1][i] = f.y;
        qt[dq * 4 + 2][i] = f.z; qt[dq * 4 + 3][i] = f.w;
    }

    float eir[8];
#pragma unroll
    for (int i = 0; i < 8; ++i)
        eir[i] = elev[b * N_ + i0 + ty * 8 + i] * (1.0f / 1000.0f);
    const float alpha = *alphap;

    u64t oacc[8][2];
    float lrow[8];
#pragma unroll
    for (int i = 0; i < 8; ++i) {
        oacc[i][0] = 0ULL; oacc[i][1] = 0ULL;
        lrow[i] = 0.0f;
    }

    const float* kb0 = g_k + (((size_t)(b * H_ + h) * N_) << 6);
    const float* vb0 = g_v + (((size_t)(b * H_ + h) * N_) << 6);
    const unsigned short* bidxb = g_bidx + (size_t)b * N_ * N_ + (size_t)i0 * N_;

    for (int jt = 0; jt < 16; ++jt) {
        const int j0 = jt * 64;
        __syncthreads();
        const float* kb = kb0 + ((size_t)j0 << 6);
        const float* vb = vb0 + ((size_t)j0 << 6);
#pragma unroll
        for (int p = 0; p < 4; ++p) {
            int idx = tid + p * 256;
            int j = idx & 63, dq = idx >> 6;
            float4 f = *(const float4*)(kb + j * 64 + dq * 4);
            kt[dq * 4 + 0][j] = f.x; kt[dq * 4 + 1][j] = f.y;
            kt[dq * 4 + 2][j] = f.z; kt[dq * 4 + 3][j] = f.w;
            int dv = idx & 15, jv = idx >> 4;
            *(float4*)&vs[jv][dv * 4] = *(const float4*)(vb + jv * 64 + dv * 4);
        }
        if (tid < 64) ejs[tid] = elev[b * N_ + j0 + tid] * (1.0f / 1000.0f);
        __syncthreads();

        u64t s2[4][4];
#pragma unroll
        for (int i = 0; i < 4; i++)
#pragma unroll
            for (int j = 0; j < 4; j++) s2[i][j] = 0ULL;
#pragma unroll 8
        for (int d = 0; d < 64; ++d) {
            ulonglong2 qa0 = *(const ulonglong2*)&qt[d][ty * 8];
            ulonglong2 qa1 = *(const ulonglong2*)&qt[d][ty * 8 + 4];
            float4 kf = *(const float4*)&kt[d][tx * 4];
            u64t ap[4] = {qa0.x, qa0.y, qa1.x, qa1.y};
            u64t bbv[4] = {dup2(kf.x), dup2(kf.y), dup2(kf.z), dup2(kf.w)};
#pragma unroll
            for (int rp = 0; rp < 4; ++rp)
#pragma unroll
                for (int c = 0; c < 4; ++c) ffma2(s2[rp][c], ap[rp], bbv[c]);
        }

        float ej[4] = {ejs[tx * 4 + 0], ejs[tx * 4 + 1], ejs[tx * 4 + 2],
                       ejs[tx * 4 + 3]};
#pragma unroll
        for (int i = 0; i < 8; ++i) {
            int rp = i >> 1, hi = i & 1;
            float sv[4];
#pragma unroll
            for (int c = 0; c < 4; ++c) {
                float2 v = *(float2*)&s2[rp][c];
                sv[c] = hi ? v.y : v.x;
            }
            uint2 bx = *(const uint2*)(bidxb + (size_t)(ty * 8 + i) * N_ + j0 + tx * 4);
            int bi[4] = {(int)(bx.x & 0xffff), (int)(bx.x >> 16),
                         (int)(bx.y & 0xffff), (int)(bx.y >> 16)};
            float e_i = eir[i];
            float p[4];
#pragma unroll
            for (int c = 0; c < 4; ++c) {
                float eb = fminf(fmaxf(-alpha * fmaxf(ej[c] - e_i, 0.f), -10.f), 0.f);
                p[c] = __expf(sv[c] * 0.125f + tbl[bi[c]] + eb);
            }
            lrow[i] += (p[0] + p[1]) + (p[2] + p[3]);
            *(float4*)&ps[ty * 8 + i][tx * 4] = make_float4(p[0], p[1], p[2], p[3]);
        }
        __syncthreads();

#pragma unroll 4
        for (int jb = 0; jb < 16; ++jb) {
            float4 pr[8];
#pragma unroll
            for (int i = 0; i < 8; ++i)
                pr[i] = *(const float4*)&ps[ty * 8 + i][jb * 4];
#pragma unroll
            for (int c = 0; c < 4; ++c) {
                ulonglong2 v2 = *(const ulonglong2*)&vs[jb * 4 + c][tx * 4];
#pragma unroll
                for (int i = 0; i < 8; ++i) {
                    float pv = (c == 0) ? pr[i].x : (c == 1) ? pr[i].y
                               : (c == 2) ? pr[i].z : pr[i].w;
                    u64t pp = dup2(pv);
                    ffma2(oacc[i][0], pp, v2.x);
                    ffma2(oacc[i][1], pp, v2.y);
                }
            }
        }
    }

#pragma unroll
    for (int i = 0; i < 8; ++i) {
        float l = lrow[i];
        l += __shfl_xor_sync(0xffffffff, l, 1);
        l += __shfl_xor_sync(0xffffffff, l, 2);
        l += __shfl_xor_sync(0xffffffff, l, 4);
        l += __shfl_xor_sync(0xffffffff, l, 8);
        float inv = 1.0f / l;
        float2 o0 = *(float2*)&oacc[i][0];
        float2 o1 = *(float2*)&oacc[i][1];
        int row = i0 + ty * 8 + i;
        float ov[4] = {o0.x * inv, o0.y * inv, o1.x * inv, o1.y * inv};
        __nv_bfloat16* rr = g_a2 + (size_t)(b * N_ + row) * 1536 + h * 64 + tx * 4;
        __nv_bfloat16 hbuf[4], lbuf[4];
#pragma unroll
        for (int c = 0; c < 4; ++c) {
            hbuf[c] = __float2bfloat16(ov[c]);
            lbuf[c] = __float2bfloat16(ov[c] - __bfloat162float(hbuf[c]));
        }
        *(uint2*)rr = *(uint2*)hbuf;
        *(uint2*)(rr + 768) = *(uint2*)lbuf;
    }
}

extern "C" void kernel_launch(void* const* d_in, const int* in_sizes, int n_in,
                              void* d_out, int out_size) {
    const float* x = (const float*)d_in[0];
    const float* coords = (const float*)d_in[1];
    const float* elev = (const float*)d_in[2];
    const float* W_qkv = (const float*)d_in[3];
    const float* W_proj = (const float*)d_in[4];
    const float* b_proj = (const float*)d_in[5];
    const float* bias_table = (const float*)d_in[6];
    const float* alpha = (const float*)d_in[7];
    float* out = (float*)d_out;

    cudaFuncSetAttribute(attn2_kernel, cudaFuncAttributeMaxDynamicSharedMemorySize,
                         ATTN_SMEM_BYTES);
    cudaFuncSetAttribute(mma_gemm<true>, cudaFuncAttributeMaxDynamicSharedMemorySize,
                         GEMM_SMEM);
    cudaFuncSetAttribute(mma_gemm<false>, cudaFuncAttributeMaxDynamicSharedMemorySize,
                         GEMM_SMEM);

    // launch index 3 (the ncu-captured one) = attn2_kernel
    prep_kernel<<<3072 + 256, 256>>>(x, coords);
    split_wt<<<dim3(ND3_ / 32, 24), dim3(32, 8)>>>(W_qkv, ND3_);
    mma_gemm<true><<<dim3(ND3_ / 128, 32), 256, GEMM_SMEM>>>(nullptr, nullptr);
    attn2_kernel<<<dim3(N_ / 128, H_, B_), 256, ATTN_SMEM_BYTES>>>(elev, bias_table, alpha);
    split_wt<<<dim3(D_ / 32, 24), dim3(32, 8)>>>(W_proj, D_);
    mma_gemm<false><<<dim3(D_ / 128, 32), 256, GEMM_SMEM>>>(b_proj, out);
}

// round 9
// speedup vs baseline: 1.4531x; 1.3729x over previous
#include <cuda_runtime.h>
#include <cuda_bf16.h>
#include <cstdint>

#define B_ 4
#define N_ 1024
#define D_ 768
#define H_ 12
#define ND3_ 2304
typedef unsigned long long u64t;

__device__ __nv_bfloat16 g_qs[B_ * H_ * N_ * 128];  // [bh][n][hi64|lo64]
__device__ __nv_bfloat16 g_ks[B_ * H_ * N_ * 128];
__device__ __nv_bfloat16 g_vs[B_ * H_ * N_ * 128];
__device__ unsigned short g_bidx[(size_t)B_ * N_ * N_];
__device__ __nv_bfloat16 g_a2[4096 * 1536];  // [m][hi(768)|lo(768)]
__device__ __nv_bfloat16 g_b2[2304 * 1536];  // [n][hi|lo]  (W transposed)

__device__ __forceinline__ uint32_t smem_u32(const void* p) {
    uint32_t a;
    asm("{ .reg .u64 t; cvta.to.shared.u64 t, %1; cvt.u32.u64 %0, t; }"
        : "=r"(a) : "l"(p));
    return a;
}
__device__ __forceinline__ void mma16816(float* c, const uint32_t* a,
                                         const uint32_t* b) {
    asm volatile(
        "mma.sync.aligned.m16n8k16.row.col.f32.bf16.bf16.f32 "
        "{%0,%1,%2,%3}, {%4,%5,%6,%7}, {%8,%9}, {%0,%1,%2,%3};"
        : "+f"(c[0]), "+f"(c[1]), "+f"(c[2]), "+f"(c[3])
        : "r"(a[0]), "r"(a[1]), "r"(a[2]), "r"(a[3]), "r"(b[0]), "r"(b[1]));
}
__device__ __forceinline__ void ldsm4(uint32_t* r, uint32_t addr) {
    asm volatile("ldmatrix.sync.aligned.m8n8.x4.shared.b16 {%0,%1,%2,%3}, [%4];"
                 : "=r"(r[0]), "=r"(r[1]), "=r"(r[2]), "=r"(r[3]) : "r"(addr));
}
__device__ __forceinline__ void ldsm4t(uint32_t* r, uint32_t addr) {
    asm volatile(
        "ldmatrix.sync.aligned.m8n8.x4.trans.shared.b16 {%0,%1,%2,%3}, [%4];"
        : "=r"(r[0]), "=r"(r[1]), "=r"(r[2]), "=r"(r[3]) : "r"(addr));
}
__device__ __forceinline__ void cp16(uint32_t dst, const void* src) {
    asm volatile("cp.async.cg.shared.global [%0], [%1], 16;" :: "r"(dst), "l"(src));
}

// --------- mma.sync bf16-split GEMM: 128x128 tile, KC=64, 3-stage ----------
#define GTILE_BYTES 18432
#define GSTAGE_BYTES (2 * GTILE_BYTES)
#define GEMM_SMEM (3 * GSTAGE_BYTES)

template <bool IS_QKV>
__global__ __launch_bounds__(256) void mma_gemm(const float* __restrict__ bias,
                                                float* __restrict__ out) {
    extern __shared__ char smem[];
    const int tid = threadIdx.x, wid = tid >> 5, lid = tid & 31;
    const int m0 = blockIdx.y * 128, n0 = blockIdx.x * 128;
    const int mw = wid >> 2, nw = wid & 3;
    const uint32_t sbase = smem_u32(smem);

    const __nv_bfloat16* a2 = g_a2 + (size_t)m0 * 1536;
    const __nv_bfloat16* b2 = g_b2 + (size_t)n0 * 1536;

    float acc[4][4][4];
#pragma unroll
    for (int i = 0; i < 4; i++)
#pragma unroll
        for (int j = 0; j < 4; j++)
#pragma unroll
            for (int k = 0; k < 4; k++) acc[i][j][k] = 0.0f;

    auto load_chunk = [&](int c, int s) {
        int p = c / 12, cc = c % 12;
        int aoff = (p == 2 ? 768 : 0) + cc * 64;
        int boff = (p == 1 ? 768 : 0) + cc * 64;
        uint32_t da = sbase + s * GSTAGE_BYTES;
        uint32_t db = da + GTILE_BYTES;
#pragma unroll
        for (int i = 0; i < 4; i++) {
            int id = tid + i * 256;
            int row = id >> 3, seg = id & 7;
            cp16(da + row * 144 + seg * 16, a2 + (size_t)row * 1536 + aoff + seg * 8);
            cp16(db + row * 144 + seg * 16, b2 + (size_t)row * 1536 + boff + seg * 8);
        }
        asm volatile("cp.async.commit_group;" ::: "memory");
    };

    load_chunk(0, 0);
    load_chunk(1, 1);

    const int q = lid >> 3, r = lid & 7;
    const int aRow = mw * 64 + (q & 1) * 8 + r;
    const int aCol = (q >> 1) * 16;
    const int bRowE = nw * 32 + (q >> 1) * 8 + r;
    const int bCol = (q & 1) * 16;

    for (int c = 0; c < 36; c++) {
        int s = c % 3;
        asm volatile("cp.async.wait_group 1;" ::: "memory");
        __syncthreads();
        if (c + 2 < 36) load_chunk(c + 2, (c + 2) % 3);
        uint32_t sAb = sbase + s * GSTAGE_BYTES;
        uint32_t sBb = sAb + GTILE_BYTES;
#pragma unroll
        for (int ks = 0; ks < 4; ks++) {
            int koff = ks * 32;
            uint32_t bfr[4][2];
#pragma unroll
            for (int p = 0; p < 2; p++) {
                uint32_t t[4];
                ldsm4(t, sBb + (bRowE + p * 16) * 144 + koff + bCol);
                bfr[p * 2 + 0][0] = t[0];
                bfr[p * 2 + 0][1] = t[1];
                bfr[p * 2 + 1][0] = t[2];
                bfr[p * 2 + 1][1] = t[3];
            }
#pragma unroll
            for (int mt = 0; mt < 4; mt++) {
                uint32_t afr[4];
                ldsm4(afr, sAb + (aRow + mt * 16) * 144 + koff + aCol);
#pragma unroll
                for (int nt = 0; nt < 4; nt++) mma16816(acc[mt][nt], afr, bfr[nt]);
            }
        }
    }

#pragma unroll
    for (int mt = 0; mt < 4; mt++) {
#pragma unroll
        for (int half = 0; half < 2; half++) {
            int m = m0 + mw * 64 + mt * 16 + (lid >> 2) + half * 8;
            int mb = m >> 10, mr = m & 1023;
#pragma unroll
            for (int nt = 0; nt < 4; nt++) {
                int ng = n0 + nw * 32 + nt * 8 + 2 * (lid & 3);
                float2 v =
                    make_float2(acc[mt][nt][half * 2], acc[mt][nt][half * 2 + 1]);
                if (IS_QKV) {
                    int which = ng / D_, nm = ng % D_, hh = nm >> 6, c0 = nm & 63;
                    __nv_bfloat16* dst =
                        ((which == 0) ? g_qs : (which == 1) ? g_ks : g_vs) +
                        ((size_t)(mb * H_ + hh) * N_ + mr) * 128 + c0;
                    __nv_bfloat162 hv, lv;
                    hv.x = __float2bfloat16(v.x);
                    hv.y = __float2bfloat16(v.y);
                    lv.x = __float2bfloat16(v.x - __bfloat162float(hv.x));
                    lv.y = __float2bfloat16(v.y - __bfloat162float(hv.y));
                    *(uint32_t*)dst = *(uint32_t*)&hv;
                    *(uint32_t*)(dst + 64) = *(uint32_t*)&lv;
                } else {
                    v.x += bias[ng];
                    v.y += bias[ng + 1];
                    *(float2*)&out[(size_t)m * D_ + ng] = v;
                }
            }
        }
    }
}

// ------------- merged prep: split_a (blocks 0..3071) + bidx (3072..3327) ----
__device__ __forceinline__ int bucket_fn(int d) {
    int ret = (d > 0) ? 16 : 0;
    int n = (d < 0) ? -d : d;
    int v;
    if (n < 8) v = n;
    else { v = 33 - __clz(n * n); v = (v > 15) ? 15 : v; }
    return ret + v;
}

__global__ __launch_bounds__(256) void prep_kernel(const float* __restrict__ X,
                                                   const float* __restrict__ coords) {
    __shared__ short cjx[1024], cjy[1024];
    const int tid = threadIdx.x;
    if (blockIdx.x < 3072) {
        int idx = blockIdx.x * 256 + tid;
        float4 v = ((const float4*)X)[idx];
        int m = idx / 192, kq = (idx % 192) * 4;
        __nv_bfloat16 h0 = __float2bfloat16(v.x), h1 = __float2bfloat16(v.y);
        __nv_bfloat16 h2 = __float2bfloat16(v.z), h3 = __float2bfloat16(v.w);
        __nv_bfloat16 l0 = __float2bfloat16(v.x - __bfloat162float(h0));
        __nv_bfloat16 l1 = __float2bfloat16(v.y - __bfloat162float(h1));
        __nv_bfloat16 l2 = __float2bfloat16(v.z - __bfloat162float(h2));
        __nv_bfloat16 l3 = __float2bfloat16(v.w - __bfloat162float(h3));
        __nv_bfloat16* rr = g_a2 + (size_t)m * 1536 + kq;
        rr[0] = h0; rr[1] = h1; rr[2] = h2; rr[3] = h3;
        rr[768] = l0; rr[769] = l1; rr[770] = l2; rr[771] = l3;
        return;
    }
    const int bid = blockIdx.x - 3072;
    const int b = bid >> 6, i0 = (bid & 63) * 16;
    for (int t = tid; t < 1024; t += 256) {
        float2 c = *(const float2*)(coords + ((size_t)b * 1024 + t) * 2);
        cjx[t] = (short)(int)(c.x * 128.0f);
        cjy[t] = (short)(int)(c.y * 128.0f);
    }
    __syncthreads();
    unsigned short* outb = g_bidx + (size_t)b * N_ * N_ + (size_t)i0 * N_;
#pragma unroll
    for (int qq = 0; qq < 16; ++qq) {
        int item = tid + qq * 256;
        int i = item >> 8, j = (item & 255) * 4;
        int cx = cjx[i0 + i], cy = cjy[i0 + i];
        ushort4 r;
        r.x = (unsigned short)((bucket_fn(cx - cjx[j]) << 5) | bucket_fn(cy - cjy[j]));
        r.y = (unsigned short)((bucket_fn(cx - cjx[j + 1]) << 5) | bucket_fn(cy - cjy[j + 1]));
        r.z = (unsigned short)((bucket_fn(cx - cjx[j + 2]) << 5) | bucket_fn(cy - cjy[j + 2]));
        r.w = (unsigned short)((bucket_fn(cx - cjx[j + 3]) << 5) | bucket_fn(cy - cjy[j + 3]));
        *(ushort4*)(outb + (size_t)i * N_ + j) = r;
    }
}

__global__ void split_wt(const float* __restrict__ W, int ncols) {
    __shared__ float t[32][33];
    int k0 = blockIdx.y * 32, n0 = blockIdx.x * 32;
    int tx = threadIdx.x, ty = threadIdx.y;  // (32,8)
#pragma unroll
    for (int i = 0; i < 4; i++)
        t[ty * 4 + i][tx] = W[(size_t)(k0 + ty * 4 + i) * ncols + n0 + tx];
    __syncthreads();
#pragma unroll
    for (int i = 0; i < 4; i++) {
        int n = n0 + ty * 4 + i;
        float x = t[tx][ty * 4 + i];
        __nv_bfloat16 h = __float2bfloat16(x);
        __nv_bfloat16 l = __float2bfloat16(x - __bfloat162float(h));
        g_b2[(size_t)n * 1536 + k0 + tx] = h;
        g_b2[(size_t)n * 1536 + 768 + k0 + tx] = l;
    }
}

// -------- tensor-core attention: i-tile 128, j-tile 64, bf16 split ---------
#define SQ_O 0       // Q [128][136 bf16] stride 272B
#define SK_O 34816   // K [64][136]
#define SV_O 52224   // V [64][136]
#define SB_O 69632   // bidx [128][72 ushort] stride 144B
#define ST_O 88064   // tbl f32[1024]
#define SE_O 92160   // ejs f32[64]
#define ATTN_SMEM 92416

__global__ __launch_bounds__(256, 2) void attn3_kernel(
    const float* __restrict__ elev, const float* __restrict__ bias_table,
    const float* __restrict__ alphap) {
    extern __shared__ char smc[];
    const uint32_t sb = smem_u32(smc);
    float* tbl = (float*)(smc + ST_O);
    float* ejs = (float*)(smc + SE_O);
    const int tid = threadIdx.x, w = tid >> 5, l = tid & 31;
    const int i0 = blockIdx.x * 128, h = blockIdx.y, b = blockIdx.z;

    for (int t = tid; t < 1024; t += 256) tbl[t] = bias_table[t * H_ + h];

    const __nv_bfloat16* qsrc = g_qs + ((size_t)(b * H_ + h) * N_ + i0) * 128;
#pragma unroll
    for (int it = 0; it < 8; it++) {
        int seg = tid + it * 256;
        int row = seg >> 4, s = seg & 15;
        cp16(sb + SQ_O + row * 272 + s * 16, qsrc + row * 128 + s * 8);
    }
    asm volatile("cp.async.commit_group;" ::: "memory");

    const int lq = l >> 2, lr = l & 3;
    const int r0g = i0 + w * 16 + lq;
    const float eir0 = elev[b * N_ + r0g] * 1e-3f;
    const float eir1 = elev[b * N_ + r0g + 8] * 1e-3f;
    const float alpha = *alphap;

    float O[8][4];
#pragma unroll
    for (int i = 0; i < 8; i++)
#pragma unroll
        for (int j = 0; j < 4; j++) O[i][j] = 0.0f;
    float lrow0 = 0.0f, lrow1 = 0.0f;

    const __nv_bfloat16* ksrc = g_ks + ((size_t)(b * H_ + h) * N_) * 128;
    const __nv_bfloat16* vsrc = g_vs + ((size_t)(b * H_ + h) * N_) * 128;
    const unsigned short* bsrc = g_bidx + ((size_t)b * N_ + i0) * N_;

    for (int jt = 0; jt < 16; jt++) {
        const int j0 = jt * 64;
        __syncthreads();
#pragma unroll
        for (int it = 0; it < 4; it++) {
            int seg = tid + it * 256;
            int row = seg >> 4, s = seg & 15;
            cp16(sb + SK_O + row * 272 + s * 16,
                 ksrc + (size_t)(j0 + row) * 128 + s * 8);
            cp16(sb + SV_O + row * 272 + s * 16,
                 vsrc + (size_t)(j0 + row) * 128 + s * 8);
            int brow = seg >> 3, bs = seg & 7;
            cp16(sb + SB_O + brow * 144 + bs * 16,
                 bsrc + (size_t)brow * N_ + j0 + bs * 8);
        }
        if (tid < 64) ejs[tid] = elev[b * N_ + j0 + tid] * 1e-3f;
        asm volatile("cp.async.commit_group;" ::: "memory");
        asm volatile("cp.async.wait_group 0;" ::: "memory");
        __syncthreads();

        // S = Q K^T : 12 k16-chunks (hh, hl, lh)
        float S[8][4];
#pragma unroll
        for (int i = 0; i < 8; i++)
#pragma unroll
            for (int j = 0; j < 4; j++) S[i][j] = 0.0f;
#pragma unroll
        for (int kc = 0; kc < 12; kc++) {
            int pass = kc >> 2, cc = kc & 3;
            int aoff = ((pass == 2 ? 64 : 0) + cc * 16) * 2;
            int boff = ((pass == 1 ? 64 : 0) + cc * 16) * 2;
            uint32_t a[4];
            ldsm4(a, sb + SQ_O + (w * 16 + (l & 15)) * 272 + aoff + (l >> 4) * 16);
#pragma unroll
            for (int jp = 0; jp < 4; jp++) {
                uint32_t t[4];
                ldsm4(t, sb + SK_O +
                             (jp * 16 + ((l >> 4) << 3) + (l & 7)) * 272 +
                             boff + ((l >> 3) & 1) * 16);
                mma16816(S[2 * jp], a, t);
                mma16816(S[2 * jp + 1], a, t + 2);
            }
        }

        // softmax (fixed-max) + pack P hi/lo fragments
        uint32_t ph[16], pl[16];
#pragma unroll
        for (int t = 0; t < 8; t++) {
            int cl = 8 * t + 2 * lr;
            uint32_t ba = *(const uint32_t*)(smc + SB_O + (w * 16 + lq) * 144 +
                                             t * 16 + lr * 4);
            uint32_t bb = *(const uint32_t*)(smc + SB_O + (w * 16 + 8 + lq) * 144 +
                                             t * 16 + lr * 4);
            float ej0 = ejs[cl], ej1 = ejs[cl + 1];
            float e00 = fminf(fmaxf(-alpha * fmaxf(ej0 - eir0, 0.f), -10.f), 0.f);
            float e01 = fminf(fmaxf(-alpha * fmaxf(ej1 - eir0, 0.f), -10.f), 0.f);
            float e10 = fminf(fmaxf(-alpha * fmaxf(ej0 - eir1, 0.f), -10.f), 0.f);
            float e11 = fminf(fmaxf(-alpha * fmaxf(ej1 - eir1, 0.f), -10.f), 0.f);
            float p0 = __expf(S[t][0] * 0.125f + tbl[ba & 0xffff] + e00);
            float p1 = __expf(S[t][1] * 0.125f + tbl[ba >> 16] + e01);
            float p2 = __expf(S[t][2] * 0.125f + tbl[bb & 0xffff] + e10);
            float p3 = __expf(S[t][3] * 0.125f + tbl[bb >> 16] + e11);
            lrow0 += p0 + p1;
            lrow1 += p2 + p3;
            __nv_bfloat162 hA, hB, lA, lB;
            hA.x = __float2bfloat16(p0); hA.y = __float2bfloat16(p1);
            hB.x = __float2bfloat16(p2); hB.y = __float2bfloat16(p3);
            lA.x = __float2bfloat16(p0 - __bfloat162float(hA.x));
            lA.y = __float2bfloat16(p1 - __bfloat162float(hA.y));
            lB.x = __float2bfloat16(p2 - __bfloat162float(hB.x));
            lB.y = __float2bfloat16(p3 - __bfloat162float(hB.y));
            ph[t * 2] = *(uint32_t*)&hA; ph[t * 2 + 1] = *(uint32_t*)&hB;
            pl[t * 2] = *(uint32_t*)&lA; pl[t * 2 + 1] = *(uint32_t*)&lB;
        }

        // O += P V  (hh + hl + lh)
#pragma unroll
        for (int c = 0; c < 4; c++) {
            const uint32_t* ah = ph + 4 * c;
            const uint32_t* al = pl + 4 * c;
            uint32_t vrow = sb + SV_O +
                            (c * 16 + (((l >> 3) & 1) << 3) + (l & 7)) * 272 +
                            (l >> 4) * 16;
#pragma unroll
            for (int dp = 0; dp < 4; dp++) {
                uint32_t tv[4];
                ldsm4t(tv, vrow + dp * 32);
                mma16816(O[2 * dp], ah, tv);
                mma16816(O[2 * dp + 1], ah, tv + 2);
                mma16816(O[2 * dp], al, tv);
                mma16816(O[2 * dp + 1], al, tv + 2);
                uint32_t tw[4];
                ldsm4t(tw, vrow + 128 + dp * 32);
                mma16816(O[2 * dp], ah, tw);
                mma16816(O[2 * dp + 1], ah, tw + 2);
            }
        }
    }

    // finalize
    lrow0 += __shfl_xor_sync(0xffffffff, lrow0, 1);
    lrow0 += __shfl_xor_sync(0xffffffff, lrow0, 2);
    lrow1 += __shfl_xor_sync(0xffffffff, lrow1, 1);
    lrow1 += __shfl_xor_sync(0xffffffff, lrow1, 2);
    float inv0 = 1.0f / lrow0, inv1 = 1.0f / lrow1;
#pragma unroll
    for (int dt = 0; dt < 8; dt++) {
        int col = h * 64 + dt * 8 + 2 * lr;
        float o0 = O[dt][0] * inv0, o1 = O[dt][1] * inv0;
        float o2 = O[dt][2] * inv1, o3 = O[dt][3] * inv1;
        __nv_bfloat16* d0 = g_a2 + (size_t)(b * N_ + r0g) * 1536 + col;
        __nv_bfloat16* d1 = g_a2 + (size_t)(b * N_ + r0g + 8) * 1536 + col;
        __nv_bfloat162 hv, lv;
        hv.x = __float2bfloat16(o0); hv.y = __float2bfloat16(o1);
        lv.x = __float2bfloat16(o0 - __bfloat162float(hv.x));
        lv.y = __float2bfloat16(o1 - __bfloat162float(hv.y));
        *(uint32_t*)d0 = *(uint32_t*)&hv;
        *(uint32_t*)(d0 + 768) = *(uint32_t*)&lv;
        hv.x = __float2bfloat16(o2); hv.y = __float2bfloat16(o3);
        lv.x = __float2bfloat16(o2 - __bfloat162float(hv.x));
        lv.y = __float2bfloat16(o3 - __bfloat162float(hv.y));
        *(uint32_t*)d1 = *(uint32_t*)&hv;
        *(uint32_t*)(d1 + 768) = *(uint32_t*)&lv;
    }
}

extern "C" void kernel_launch(void* const* d_in, const int* in_sizes, int n_in,
                              void* d_out, int out_size) {
    const float* x = (const float*)d_in[0];
    const float* coords = (const float*)d_in[1];
    const float* elev = (const float*)d_in[2];
    const float* W_qkv = (const float*)d_in[3];
    const float* W_proj = (const float*)d_in[4];
    const float* b_proj = (const float*)d_in[5];
    const float* bias_table = (const float*)d_in[6];
    const float* alpha = (const float*)d_in[7];
    float* out = (float*)d_out;

    cudaFuncSetAttribute(attn3_kernel, cudaFuncAttributeMaxDynamicSharedMemorySize,
                         ATTN_SMEM);
    cudaFuncSetAttribute(mma_gemm<true>, cudaFuncAttributeMaxDynamicSharedMemorySize,
                         GEMM_SMEM);
    cudaFuncSetAttribute(mma_gemm<false>, cudaFuncAttributeMaxDynamicSharedMemorySize,
                         GEMM_SMEM);

    // launch index 3 (the ncu-captured one) = attn3_kernel
    prep_kernel<<<3072 + 256, 256>>>(x, coords);
    split_wt<<<dim3(ND3_ / 32, 24), dim3(32, 8)>>>(W_qkv, ND3_);
    mma_gemm<true><<<dim3(ND3_ / 128, 32), 256, GEMM_SMEM>>>(nullptr, nullptr);
    attn3_kernel<<<dim3(N_ / 128, H_, B_), 256, ATTN_SMEM>>>(elev, bias_table, alpha);
    split_wt<<<dim3(D_ / 32, 24), dim3(32, 8)>>>(W_proj, D_);
    mma_gemm<false><<<dim3(D_ / 128, 32), 256, GEMM_SMEM>>>(b_proj, out);
}